// round 6
// baseline (speedup 1.0000x reference)
#include <cuda_runtime.h>
#include <math.h>

#define BATCH 8
#define CH    2048
#define HW    4096
#define NSEL  (CH*3)

__device__ float g_stats[BATCH][CH][3];
__device__ float g_gate[BATCH][CH];

// ---------------------------------------------------------------------------
// stats(b): one block per channel, 256 threads, 4 float4/thread.
// Default cache policy: we WANT this 32MB batch resident in L2 for scale(b).
// ---------------------------------------------------------------------------
__global__ __launch_bounds__(256) void k_stats_b(const float* __restrict__ x, int b) {
    int c = blockIdx.x;
    const float4* p = reinterpret_cast<const float4*>(x)
                    + ((size_t)(b * CH + c)) * (HW / 4);

    float s = 0.f, s2 = 0.f, mx = -INFINITY;
#pragma unroll
    for (int i = 0; i < 4; i++) {
        float4 v = p[threadIdx.x + i * 256];
        s  += (v.x + v.y) + (v.z + v.w);
        s2 += (v.x * v.x + v.y * v.y) + (v.z * v.z + v.w * v.w);
        mx = fmaxf(mx, fmaxf(fmaxf(v.x, v.y), fmaxf(v.z, v.w)));
    }
#pragma unroll
    for (int o = 16; o; o >>= 1) {
        s  += __shfl_xor_sync(0xffffffffu, s, o);
        s2 += __shfl_xor_sync(0xffffffffu, s2, o);
        mx = fmaxf(mx, __shfl_xor_sync(0xffffffffu, mx, o));
    }
    __shared__ float ss[8], ss2[8], sm[8];
    int w = threadIdx.x >> 5;
    if ((threadIdx.x & 31) == 0) { ss[w] = s; ss2[w] = s2; sm[w] = mx; }
    __syncthreads();
    if (threadIdx.x == 0) {
        s = ss[0]; s2 = ss2[0]; mx = sm[0];
#pragma unroll
        for (int i = 1; i < 8; i++) { s += ss[i]; s2 += ss2[i]; mx = fmaxf(mx, sm[i]); }
        float mean = s / (float)HW;
        float var  = (s2 - (float)HW * mean * mean) / (float)(HW - 1);
        var = fmaxf(var, 0.f);
        g_stats[b][c][0] = mean;
        g_stats[b][c][1] = mx;
        g_stats[b][c][2] = sqrtf(var);
    }
}

// ---------------------------------------------------------------------------
// median(b) + gate(b): 1 block, 1024 threads. Exact median (avg of ranks
// 3071/3072) via single 4-pass radix select + tie/min-greater fixup.
// ---------------------------------------------------------------------------
__device__ __forceinline__ unsigned f2k(float f) {
    unsigned u = __float_as_uint(f);
    return (u & 0x80000000u) ? ~u : (u | 0x80000000u);
}
__device__ __forceinline__ float k2f(unsigned k) {
    unsigned u = (k & 0x80000000u) ? (k ^ 0x80000000u) : ~k;
    return __uint_as_float(u);
}

__global__ __launch_bounds__(1024) void k_median_b(const float* __restrict__ cfc_w,
                                                   const float* __restrict__ bn_w,
                                                   const float* __restrict__ bn_b,
                                                   int b) {
    __shared__ unsigned keys[NSEL];          // 24 KB
    __shared__ unsigned hist[16][256];       // 16 KB
    __shared__ unsigned s_prefix;
    __shared__ int      s_rank;
    __shared__ unsigned s_eq;
    __shared__ unsigned s_wmin[32];

    int tid = threadIdx.x, lane = tid & 31, warp = tid >> 5;
    const float* st = &g_stats[b][0][0];

    for (int i = tid; i < NSEL; i += 1024) keys[i] = f2k(st[i]);
    __syncthreads();

    int rank = NSEL / 2 - 1;                 // 3071
    unsigned prefix = 0;
    for (int shift = 24; shift >= 0; shift -= 8) {
        for (int i = tid; i < 16 * 256; i += 1024) (&hist[0][0])[i] = 0u;
        __syncthreads();
        unsigned mhi = (shift == 24) ? 0u : (0xFFFFFFFFu << (shift + 8));
        int grp = tid >> 6;
        for (int i = tid; i < NSEL; i += 1024) {
            unsigned k = keys[i];
            if ((k & mhi) == prefix)
                atomicAdd(&hist[grp][(k >> shift) & 255u], 1u);
        }
        __syncthreads();
        if (tid < 256) {
            unsigned a = 0;
#pragma unroll
            for (int j = 0; j < 16; j++) a += hist[j][tid];
            hist[0][tid] = a;
        }
        __syncthreads();
        if (warp == 0) {
            unsigned part = 0;
#pragma unroll
            for (int j = 0; j < 8; j++) part += hist[0][lane * 8 + j];
            unsigned p = part;
#pragma unroll
            for (int o = 1; o < 32; o <<= 1) {
                unsigned t = __shfl_up_sync(0xffffffffu, p, o);
                if (lane >= o) p += t;
            }
            unsigned excl = p - part;
            unsigned mask = __ballot_sync(0xffffffffu, (int)excl <= rank);
            int lead = 31 - __clz(mask);
            if (lane == lead) {
                int r = rank - (int)excl;
                int d = lane * 8;
                unsigned cnt = 0;
#pragma unroll
                for (int j = 0; j < 8; j++) {
                    cnt = hist[0][lane * 8 + j];
                    if (r < (int)cnt) { d = lane * 8 + j; break; }
                    r -= (int)cnt;
                }
                s_prefix = prefix | ((unsigned)d << shift);
                s_rank   = r;
                s_eq     = cnt;
            }
        }
        __syncthreads();
        prefix = s_prefix;
        rank   = s_rank;
    }

    unsigned k0 = prefix;
    float v0 = k2f(k0), v1;
    if ((unsigned)(rank + 1) < s_eq) {
        v1 = v0;
    } else {
        unsigned m = 0xFFFFFFFFu;
        for (int i = tid; i < NSEL; i += 1024) {
            unsigned k = keys[i];
            if (k > k0) m = min(m, k);
        }
#pragma unroll
        for (int o = 16; o; o >>= 1) m = min(m, __shfl_xor_sync(0xffffffffu, m, o));
        if (lane == 0) s_wmin[warp] = m;
        __syncthreads();
        if (tid == 0) {
            unsigned mm = s_wmin[0];
#pragma unroll
            for (int j = 1; j < 32; j++) mm = min(mm, s_wmin[j]);
            s_prefix = mm;
        }
        __syncthreads();
        v1 = k2f(s_prefix);
    }
    float med = 0.5f * (v0 + v1);

    const float inv = rsqrtf(1.0f + 1e-5f);
    for (int c = tid; c < CH; c += 1024) {
        float u0 = st[c * 3 + 0] - med;
        float u1 = st[c * 3 + 1] - med;
        float u2 = st[c * 3 + 2] - med;
        float z = (u0 * u0 * u0) * cfc_w[c * 3 + 0]
                + (u1 * u1 * u1) * cfc_w[c * 3 + 1]
                + (u2 * u2 * u2) * cfc_w[c * 3 + 2];
        z = z * inv * bn_w[c] + bn_b[c];
        g_gate[b][c] = 1.f / (1.f + expf(-z));
    }
}

// ---------------------------------------------------------------------------
// scale(b): one block per channel. Reads hit L2 (populated by stats(b)),
// streaming stores so the 32MB of output doesn't evict the next batch's x.
// ---------------------------------------------------------------------------
__global__ __launch_bounds__(256) void k_scale_b(const float* __restrict__ x,
                                                 float* __restrict__ out, int b) {
    int c = blockIdx.x;
    float g = g_gate[b][c];
    const float4* px = reinterpret_cast<const float4*>(x)
                     + ((size_t)(b * CH + c)) * (HW / 4);
    float4*       po = reinterpret_cast<float4*>(out)
                     + ((size_t)(b * CH + c)) * (HW / 4);
#pragma unroll
    for (int i = 0; i < 4; i++) {
        float4 v = px[threadIdx.x + i * 256];
        v.x *= g; v.y *= g; v.z *= g; v.w *= g;
        __stcs(po + threadIdx.x + i * 256, v);
    }
}

// ---------------------------------------------------------------------------
// Host: per-batch pipeline across 3 streams (graph-capturable fork/join).
//   stream0 (capture): stats(0..7) chain
//   s2: median(b) after stats(b)      — hides behind scale(b-1)
//   s1: scale(b) after median(b)      — co-runs with stats(b+1)
// ---------------------------------------------------------------------------
static cudaStream_t s1 = nullptr, s2 = nullptr;
static cudaEvent_t  evS[BATCH], evM[BATCH], evJ;

extern "C" void kernel_launch(void* const* d_in, const int* in_sizes, int n_in,
                              void* d_out, int out_size) {
    const float* x     = (const float*)d_in[0];
    const float* cfc_w = (const float*)d_in[1];
    const float* bn_w  = (const float*)d_in[2];
    const float* bn_b  = (const float*)d_in[3];
    float* out = (float*)d_out;

    if (!s1) {  // one-time host-side infra (no device memory involved)
        cudaStreamCreateWithFlags(&s1, cudaStreamNonBlocking);
        cudaStreamCreateWithFlags(&s2, cudaStreamNonBlocking);
        for (int b = 0; b < BATCH; b++) {
            cudaEventCreateWithFlags(&evS[b], cudaEventDisableTiming);
            cudaEventCreateWithFlags(&evM[b], cudaEventDisableTiming);
        }
        cudaEventCreateWithFlags(&evJ, cudaEventDisableTiming);
    }

    // stats chain on the capture stream
    for (int b = 0; b < BATCH; b++) {
        k_stats_b<<<CH, 256>>>(x, b);
        cudaEventRecord(evS[b], 0);
    }
    // median + scale chains forked off
    for (int b = 0; b < BATCH; b++) {
        cudaStreamWaitEvent(s2, evS[b], 0);
        k_median_b<<<1, 1024, 0, s2>>>(cfc_w, bn_w, bn_b, b);
        cudaEventRecord(evM[b], s2);

        cudaStreamWaitEvent(s1, evM[b], 0);
        k_scale_b<<<CH, 256, 0, s1>>>(x, out, b);
    }
    // join everything back to the capture stream
    cudaEventRecord(evJ, s1);
    cudaStreamWaitEvent(0, evJ, 0);
}

// round 7
// speedup vs baseline: 1.4978x; 1.4978x over previous
#include <cuda_runtime.h>
#include <math.h>

#define BATCH 8
#define CH    2048
#define HW    4096
#define NBC   (BATCH*CH)
#define NSEL  (CH*3)

__device__ float g_stats[NBC * 3];   // [b,c,{mean,max,std}]
__device__ float g_gate[NBC];

// ---------------------------------------------------------------------------
// K1: per-(b,c) stats. REVERSE block order so the lowest addresses of x are
// the freshest content in L2 when K1 ends (K3 reads them first).
// ---------------------------------------------------------------------------
__global__ __launch_bounds__(256) void k_stats(const float* __restrict__ x) {
    int bc = NBC - 1 - blockIdx.x;
    const float4* p = reinterpret_cast<const float4*>(x) + (size_t)bc * (HW / 4);

    float s = 0.f, s2 = 0.f, mx = -INFINITY;
#pragma unroll
    for (int i = 0; i < 4; i++) {
        float4 v = p[threadIdx.x + i * 256];
        s  += (v.x + v.y) + (v.z + v.w);
        s2 += (v.x * v.x + v.y * v.y) + (v.z * v.z + v.w * v.w);
        mx = fmaxf(mx, fmaxf(fmaxf(v.x, v.y), fmaxf(v.z, v.w)));
    }
#pragma unroll
    for (int o = 16; o; o >>= 1) {
        s  += __shfl_xor_sync(0xffffffffu, s, o);
        s2 += __shfl_xor_sync(0xffffffffu, s2, o);
        mx = fmaxf(mx, __shfl_xor_sync(0xffffffffu, mx, o));
    }
    __shared__ float ss[8], ss2[8], sm[8];
    int w = threadIdx.x >> 5;
    if ((threadIdx.x & 31) == 0) { ss[w] = s; ss2[w] = s2; sm[w] = mx; }
    __syncthreads();
    if (threadIdx.x == 0) {
        s = ss[0]; s2 = ss2[0]; mx = sm[0];
#pragma unroll
        for (int i = 1; i < 8; i++) { s += ss[i]; s2 += ss2[i]; mx = fmaxf(mx, sm[i]); }
        float mean = s / (float)HW;
        float var  = (s2 - (float)HW * mean * mean) / (float)(HW - 1);
        var = fmaxf(var, 0.f);
        float* o = g_stats + (size_t)bc * 3;
        o[0] = mean;
        o[1] = mx;
        o[2] = sqrtf(var);
    }
}

// ---------------------------------------------------------------------------
// K2: per-batch median (avg of ranks 3071/3072) + gate. 8 blocks, 1024 thr.
// Single 4-pass radix select + tie/min-greater fixup; warp shuffle-scan digit
// search. (Validated structure from R3.)
// ---------------------------------------------------------------------------
__device__ __forceinline__ unsigned f2k(float f) {
    unsigned u = __float_as_uint(f);
    return (u & 0x80000000u) ? ~u : (u | 0x80000000u);
}
__device__ __forceinline__ float k2f(unsigned k) {
    unsigned u = (k & 0x80000000u) ? (k ^ 0x80000000u) : ~k;
    return __uint_as_float(u);
}

__global__ __launch_bounds__(1024) void k_median_gate(const float* __restrict__ cfc_w,
                                                      const float* __restrict__ bn_w,
                                                      const float* __restrict__ bn_b) {
    __shared__ unsigned keys[NSEL];
    __shared__ unsigned hist[16][256];
    __shared__ unsigned s_prefix;
    __shared__ int      s_rank;
    __shared__ unsigned s_eq;
    __shared__ unsigned s_wmin[32];

    int b = blockIdx.x, tid = threadIdx.x;
    int lane = tid & 31, warp = tid >> 5;
    const float* st = g_stats + (size_t)b * NSEL;

    for (int i = tid; i < NSEL; i += 1024) keys[i] = f2k(st[i]);
    __syncthreads();

    int rank = NSEL / 2 - 1;                 // 3071
    unsigned prefix = 0;
    for (int shift = 24; shift >= 0; shift -= 8) {
        for (int i = tid; i < 16 * 256; i += 1024) (&hist[0][0])[i] = 0u;
        __syncthreads();
        unsigned mhi = (shift == 24) ? 0u : (0xFFFFFFFFu << (shift + 8));
        int grp = tid >> 6;
        for (int i = tid; i < NSEL; i += 1024) {
            unsigned k = keys[i];
            if ((k & mhi) == prefix)
                atomicAdd(&hist[grp][(k >> shift) & 255u], 1u);
        }
        __syncthreads();
        if (tid < 256) {
            unsigned a = 0;
#pragma unroll
            for (int j = 0; j < 16; j++) a += hist[j][tid];
            hist[0][tid] = a;
        }
        __syncthreads();
        if (warp == 0) {
            unsigned part = 0;
#pragma unroll
            for (int j = 0; j < 8; j++) part += hist[0][lane * 8 + j];
            unsigned p = part;
#pragma unroll
            for (int o = 1; o < 32; o <<= 1) {
                unsigned t = __shfl_up_sync(0xffffffffu, p, o);
                if (lane >= o) p += t;
            }
            unsigned excl = p - part;
            unsigned mask = __ballot_sync(0xffffffffu, (int)excl <= rank);
            int lead = 31 - __clz(mask);
            if (lane == lead) {
                int r = rank - (int)excl;
                int d = lane * 8;
                unsigned cnt = 0;
#pragma unroll
                for (int j = 0; j < 8; j++) {
                    cnt = hist[0][lane * 8 + j];
                    if (r < (int)cnt) { d = lane * 8 + j; break; }
                    r -= (int)cnt;
                }
                s_prefix = prefix | ((unsigned)d << shift);
                s_rank   = r;
                s_eq     = cnt;
            }
        }
        __syncthreads();
        prefix = s_prefix;
        rank   = s_rank;
    }

    unsigned k0 = prefix;
    float v0 = k2f(k0), v1;
    if ((unsigned)(rank + 1) < s_eq) {
        v1 = v0;
    } else {
        unsigned m = 0xFFFFFFFFu;
        for (int i = tid; i < NSEL; i += 1024) {
            unsigned k = keys[i];
            if (k > k0) m = min(m, k);
        }
#pragma unroll
        for (int o = 16; o; o >>= 1) m = min(m, __shfl_xor_sync(0xffffffffu, m, o));
        if (lane == 0) s_wmin[warp] = m;
        __syncthreads();
        if (tid == 0) {
            unsigned mm = s_wmin[0];
#pragma unroll
            for (int j = 1; j < 32; j++) mm = min(mm, s_wmin[j]);
            s_prefix = mm;
        }
        __syncthreads();
        v1 = k2f(s_prefix);
    }
    float med = 0.5f * (v0 + v1);

    const float inv = rsqrtf(1.0f + 1e-5f);
    for (int c = tid; c < CH; c += 1024) {
        float u0 = st[c * 3 + 0] - med;
        float u1 = st[c * 3 + 1] - med;
        float u2 = st[c * 3 + 2] - med;
        float z = (u0 * u0 * u0) * cfc_w[c * 3 + 0]
                + (u1 * u1 * u1) * cfc_w[c * 3 + 1]
                + (u2 * u2 * u2) * cfc_w[c * 3 + 2];
        z = z * inv * bn_w[c] + bn_b[c];
        g_gate[b * CH + c] = 1.f / (1.f + expf(-z));
    }
}

// ---------------------------------------------------------------------------
// K3: out = x * g. 2 channels per block, 8 independent float4 loads per
// thread (MLP=8) then 8 streaming stores. Forward order → early blocks hit
// K1's L2 leftovers at low addresses.
// ---------------------------------------------------------------------------
__global__ __launch_bounds__(256) void k_scale(const float* __restrict__ x,
                                               float* __restrict__ out) {
    int c0 = blockIdx.x * 2;                         // two consecutive channels
    size_t base = (size_t)c0 * (HW / 4);             // in float4 units
    const float4* px = reinterpret_cast<const float4*>(x) + base;
    float4*       po = reinterpret_cast<float4*>(out)     + base;
    float g0 = g_gate[c0];
    float g1 = g_gate[c0 + 1];

    float4 v[8];
#pragma unroll
    for (int i = 0; i < 8; i++)
        v[i] = __ldcs(px + threadIdx.x + i * 256);   // 8 outstanding LDG.128
#pragma unroll
    for (int i = 0; i < 8; i++) {
        float g = (i < 4) ? g0 : g1;                 // first 1024 float4 = c0
        v[i].x *= g; v[i].y *= g; v[i].z *= g; v[i].w *= g;
        __stcs(po + threadIdx.x + i * 256, v[i]);
    }
}

extern "C" void kernel_launch(void* const* d_in, const int* in_sizes, int n_in,
                              void* d_out, int out_size) {
    const float* x     = (const float*)d_in[0];
    const float* cfc_w = (const float*)d_in[1];
    const float* bn_w  = (const float*)d_in[2];
    const float* bn_b  = (const float*)d_in[3];
    float* out = (float*)d_out;

    k_stats<<<NBC, 256>>>(x);
    k_median_gate<<<BATCH, 1024>>>(cfc_w, bn_w, bn_b);
    k_scale<<<NBC / 2, 256>>>(x, out);
}